// round 6
// baseline (speedup 1.0000x reference)
#include <cuda_runtime.h>

// out[e] = dot(h[src[e]], h[dst[e]]); h: [N,128] fp32, E ~3.2M, int32 idx.
//
// R4 shape (8 lanes/edge, 4 edges/warp, 32 lines in flight per warp) plus:
//  - software pipeline: next iteration's src row + indices prefetched during
//    current iteration's compute -> warp keeps loads outstanding through the
//    FMA/shuffle tail (duty cycle ~1 instead of ~0.5)
//  - 2-accumulator FMA tree (shorter serial tail)
//  - streaming hints (__ldcs/__stcs) for edge lists + output so they don't
//    evict the L2-resident h table (51MB of 126MB L2).

#define F4_PER_ROW 32   // 128 floats = 32 float4

__global__ void __launch_bounds__(256, 4)
edge_dot_kernel(const float4* __restrict__ h4,
                const int* __restrict__ src,
                const int* __restrict__ dst,
                float* __restrict__ out,
                int n_edges)
{
    const int lane  = threadIdx.x & 31;
    const int sub   = lane & 7;        // 0..7: lane within 8-lane edge group

    const int warp_id  = (blockIdx.x * blockDim.x + threadIdx.x) >> 5;
    const int n_warps  = (gridDim.x * blockDim.x) >> 5;
    const int e_stride = n_warps * 4;

    int e = warp_id * 4 + ((lane >> 3) & 3);

    if (e >= n_edges) return;

    // ---- pipeline prologue: indices + src row for first edge ----
    int s_cur = __ldcs(&src[e]);
    int d_cur = __ldcs(&dst[e]);

    const float4* __restrict__ hs = h4 + (size_t)s_cur * F4_PER_ROW;
    float4 a0 = __ldg(&hs[sub +  0]);
    float4 a1 = __ldg(&hs[sub +  8]);
    float4 a2 = __ldg(&hs[sub + 16]);
    float4 a3 = __ldg(&hs[sub + 24]);

    for (; e < n_edges; ) {
        const int e_next = e + e_stride;

        // Prefetch next indices early (L2 latency hidden behind row loads)
        int s_nxt = 0, d_nxt = 0;
        const bool more = (e_next < n_edges);
        if (more) {
            s_nxt = __ldcs(&src[e_next]);
            d_nxt = __ldcs(&dst[e_next]);
        }

        // Current dst row (consumed this iteration)
        const float4* __restrict__ hd = h4 + (size_t)d_cur * F4_PER_ROW;
        float4 b0 = __ldg(&hd[sub +  0]);
        float4 b1 = __ldg(&hd[sub +  8]);
        float4 b2 = __ldg(&hd[sub + 16]);
        float4 b3 = __ldg(&hd[sub + 24]);

        // Two-accumulator dot
        float p = a0.x * b0.x;
        float q = a0.y * b0.y;
        p = fmaf(a0.z, b0.z, p);  q = fmaf(a0.w, b0.w, q);
        p = fmaf(a1.x, b1.x, p);  q = fmaf(a1.y, b1.y, q);
        p = fmaf(a1.z, b1.z, p);  q = fmaf(a1.w, b1.w, q);
        p = fmaf(a2.x, b2.x, p);  q = fmaf(a2.y, b2.y, q);
        p = fmaf(a2.z, b2.z, p);  q = fmaf(a2.w, b2.w, q);
        p = fmaf(a3.x, b3.x, p);  q = fmaf(a3.y, b3.y, q);
        p = fmaf(a3.z, b3.z, p);  q = fmaf(a3.w, b3.w, q);

        // Prefetch next src row NOW — outstanding through the reduce tail
        if (more) {
            const float4* __restrict__ hn = h4 + (size_t)s_nxt * F4_PER_ROW;
            a0 = __ldg(&hn[sub +  0]);
            a1 = __ldg(&hn[sub +  8]);
            a2 = __ldg(&hn[sub + 16]);
            a3 = __ldg(&hn[sub + 24]);
        }

        float sum = p + q;
        sum += __shfl_xor_sync(0xFFFFFFFFu, sum, 4);
        sum += __shfl_xor_sync(0xFFFFFFFFu, sum, 2);
        sum += __shfl_xor_sync(0xFFFFFFFFu, sum, 1);

        if (sub == 0)
            __stcs(&out[e], sum);

        if (!more) break;
        e = e_next;
        d_cur = d_nxt;
    }
}

extern "C" void kernel_launch(void* const* d_in, const int* in_sizes, int n_in,
                              void* d_out, int out_size)
{
    const float4* h4  = (const float4*)d_in[0];
    const int*    src = (const int*)d_in[1];
    const int*    dst = (const int*)d_in[2];
    float*        out = (float*)d_out;

    const int n_edges = in_sizes[1];

    // 4 blocks/SM x 148 SMs = 592 persistent blocks, 256 threads each.
    const int blocks = 592;
    edge_dot_kernel<<<blocks, 256>>>(h4, src, dst, out, n_edges);
}

// round 7
// speedup vs baseline: 1.1002x; 1.1002x over previous
#include <cuda_runtime.h>

// out[e] = dot(h[src[e]], h[dst[e]]); h: [N,128] fp32, E ~3.2M, int32 idx.
//
// R4 winning structure: 8 lanes/edge, 4 edges/warp, 8 independent LDG.128
// per lane-group (32 x 128B lines outstanding per warp), persistent
// grid-stride loop with index prefetch. Only change vs R4: occupancy forced
// to 6 blocks/SM (reg cap 42) -> 48 resident warps/SM, +20% outstanding
// L2 requests chip-wide.

#define F4_PER_ROW 32   // 128 floats = 32 float4

__global__ void __launch_bounds__(256, 6)
edge_dot_kernel(const float4* __restrict__ h4,
                const int* __restrict__ src,
                const int* __restrict__ dst,
                float* __restrict__ out,
                int n_edges)
{
    const int lane  = threadIdx.x & 31;
    const int group = lane >> 3;       // 0..3: edge slot within warp
    const int sub   = lane & 7;        // 0..7: lane within edge group

    const int warp_id  = (blockIdx.x * blockDim.x + threadIdx.x) >> 5;
    const int n_warps  = (gridDim.x * blockDim.x) >> 5;
    const int e_stride = n_warps * 4;

    int e = warp_id * 4 + group;

    // Prefetch first indices
    int s_pre = 0, d_pre = 0;
    if (e < n_edges) {
        s_pre = __ldg(&src[e]);
        d_pre = __ldg(&dst[e]);
    }

    for (; e < n_edges; e += e_stride) {
        const int s = s_pre;
        const int d = d_pre;

        // Prefetch next iteration's indices (overlaps with row loads below)
        const int e_next = e + e_stride;
        if (e_next < n_edges) {
            s_pre = __ldg(&src[e_next]);
            d_pre = __ldg(&dst[e_next]);
        }

        const float4* __restrict__ hs = h4 + (size_t)s * F4_PER_ROW;
        const float4* __restrict__ hd = h4 + (size_t)d * F4_PER_ROW;

        // 8 independent 16B loads -> 8 x 128B lines in flight per group
        float4 a0 = __ldg(&hs[sub +  0]);
        float4 a1 = __ldg(&hs[sub +  8]);
        float4 a2 = __ldg(&hs[sub + 16]);
        float4 a3 = __ldg(&hs[sub + 24]);
        float4 b0 = __ldg(&hd[sub +  0]);
        float4 b1 = __ldg(&hd[sub +  8]);
        float4 b2 = __ldg(&hd[sub + 16]);
        float4 b3 = __ldg(&hd[sub + 24]);

        float sum;
        sum = a0.x * b0.x;
        sum = fmaf(a0.y, b0.y, sum);
        sum = fmaf(a0.z, b0.z, sum);
        sum = fmaf(a0.w, b0.w, sum);
        sum = fmaf(a1.x, b1.x, sum);
        sum = fmaf(a1.y, b1.y, sum);
        sum = fmaf(a1.z, b1.z, sum);
        sum = fmaf(a1.w, b1.w, sum);
        sum = fmaf(a2.x, b2.x, sum);
        sum = fmaf(a2.y, b2.y, sum);
        sum = fmaf(a2.z, b2.z, sum);
        sum = fmaf(a2.w, b2.w, sum);
        sum = fmaf(a3.x, b3.x, sum);
        sum = fmaf(a3.y, b3.y, sum);
        sum = fmaf(a3.z, b3.z, sum);
        sum = fmaf(a3.w, b3.w, sum);

        // Reduce within 8-lane group
        sum += __shfl_xor_sync(0xFFFFFFFFu, sum, 4);
        sum += __shfl_xor_sync(0xFFFFFFFFu, sum, 2);
        sum += __shfl_xor_sync(0xFFFFFFFFu, sum, 1);

        if (sub == 0)
            out[e] = sum;
    }
}

extern "C" void kernel_launch(void* const* d_in, const int* in_sizes, int n_in,
                              void* d_out, int out_size)
{
    const float4* h4  = (const float4*)d_in[0];
    const int*    src = (const int*)d_in[1];
    const int*    dst = (const int*)d_in[2];
    float*        out = (float*)d_out;

    const int n_edges = in_sizes[1];

    // 6 blocks/SM x 148 SMs = 888 persistent blocks.
    const int blocks = 888;
    edge_dot_kernel<<<blocks, 256>>>(h4, src, dst, out, n_edges);
}